// round 2
// baseline (speedup 1.0000x reference)
#include <cuda_runtime.h>
#include <math.h>

#define NT 256
#define G 16
#define MAXSTEPS 4096
#define SMEM_FLOATS 40652
#define SMEM_BYTES (SMEM_FLOATS * 4)

// ---------------- persistent device state (no allocations allowed) ----------
__device__ float g_T[MAXSTEPS * 1024];   // per-step time-side gate contribution + folded biases
__device__ float g_UT[MAXSTEPS * 128];   // per-step tanh(LN(time enc layer1))
__device__ float g_M1[1024 * 128];       // w_ih[:, :128] @ se_w2
__device__ float g_M2t[128 * 1024];      // transpose of w_ih[:, 128:] @ te_w2
__device__ float g_Kc[1024];             // folded constant bias
__device__ float g_h[256];               // LSTM hidden state (cross-CTA)
__device__ float g_vd[256];              // [v1(128) | d1(128)] head layer-1 outputs
__device__ float g_curr[4];
__device__ unsigned g_cnt[2];
__device__ unsigned g_rel[2];

__device__ __forceinline__ float sigm(float x) { return 1.0f / (1.0f + expf(-x)); }

__device__ __forceinline__ unsigned ld_cv(const unsigned* p) {
    unsigned v;
    asm volatile("ld.global.cv.u32 %0, [%1];" : "=r"(v) : "l"(p));
    return v;
}

// sum over all 256 threads (inactive lanes must pass 0)
__device__ __forceinline__ float blocksum256(float v, float* red) {
    int lane = threadIdx.x & 31, w = threadIdx.x >> 5;
#pragma unroll
    for (int o = 16; o > 0; o >>= 1) v += __shfl_down_sync(0xffffffffu, v, o);
    if (lane == 0) red[w] = v;
    __syncthreads();
    float s = red[0] + red[1] + red[2] + red[3] + red[4] + red[5] + red[6] + red[7];
    __syncthreads();
    return s;
}

// sum over 128 threads (4 warps)
__device__ __forceinline__ float blocksum128(float v, float* red) {
    int lane = threadIdx.x & 31, w = threadIdx.x >> 5;
#pragma unroll
    for (int o = 16; o > 0; o >>= 1) v += __shfl_down_sync(0xffffffffu, v, o);
    if (lane == 0) red[w] = v;
    __syncthreads();
    float s = red[0] + red[1] + red[2] + red[3];
    __syncthreads();
    return s;
}

// grid barrier: monotonic phase, no reset hazard
__device__ __forceinline__ void gridbar(int k, unsigned ph) {
    __syncthreads();
    if (threadIdx.x == 0) {
        __threadfence();
        unsigned a = atomicAdd(&g_cnt[k], 1u);
        if (a + 1u == ph * (unsigned)G) {
            atomicExch(&g_rel[k], ph);
        } else {
            while (ld_cv(&g_rel[k]) < ph) __nanosleep(32);
        }
        __threadfence();
    }
    __syncthreads();
}

// ---------------- precompute M1, M2t, Kc ----------------
__global__ void k_M(const float* __restrict__ w_ih, const float* __restrict__ se_w2,
                    const float* __restrict__ te_w2, const float* __restrict__ se_b2,
                    const float* __restrict__ te_b2, const float* __restrict__ b_ih,
                    const float* __restrict__ b_hh) {
    int r = blockIdx.x, j = threadIdx.x;  // 1024 blocks x 128 threads
    const float* wr = w_ih + r * 256;
    float s1 = 0.f, s2 = 0.f;
    for (int i = 0; i < 128; i++) s1 += wr[i] * se_w2[i * 128 + j];
    for (int i = 0; i < 128; i++) s2 += wr[128 + i] * te_w2[i * 128 + j];
    g_M1[r * 128 + j] = s1;
    g_M2t[j * 1024 + r] = s2;
    if (j == 0) {
        float kc = b_ih[r] + b_hh[r];
        for (int i = 0; i < 128; i++) kc += wr[i] * se_b2[i] + wr[128 + i] * te_b2[i];
        g_Kc[r] = kc;
    }
}

// ---------------- setup: barriers, curr0, out row0, h0 ----------------
__global__ void k_setup(const float* __restrict__ psi_re, const float* __restrict__ psi_im,
                        const float* __restrict__ t_start,
                        const float* __restrict__ se_w1, const float* __restrict__ se_b1,
                        const float* __restrict__ se_lng, const float* __restrict__ se_lnb,
                        const float* __restrict__ se_w2, const float* __restrict__ se_b2,
                        const float* __restrict__ te_w1, const float* __restrict__ te_b1,
                        const float* __restrict__ te_lng, const float* __restrict__ te_lnb,
                        const float* __restrict__ te_w2, const float* __restrict__ te_b2,
                        const float* __restrict__ hi_w, const float* __restrict__ hi_b,
                        float* __restrict__ out) {
    __shared__ float curr[4], u[128], comb[256], red[8];
    int tid = threadIdx.x;
    if (tid == 0) { g_cnt[0] = 0; g_cnt[1] = 0; g_rel[0] = 0; g_rel[1] = 0; }
    if (tid < 4) {
        float v = (tid < 2) ? psi_re[tid] : psi_im[tid - 2];
        curr[tid] = v; g_curr[tid] = v; out[tid] = v;
    }
    __syncthreads();
    // enc_state(curr0)
    float z = 0.f;
    if (tid < 128) {
        const float* w = se_w1 + tid * 4;
        z = se_b1[tid] + w[0] * curr[0] + w[1] * curr[1] + w[2] * curr[2] + w[3] * curr[3];
    }
    float m = blocksum256(tid < 128 ? z : 0.f, red) * 0.0078125f;
    float d = (tid < 128) ? z - m : 0.f;
    float var = blocksum256(d * d, red) * 0.0078125f;
    if (tid < 128) u[tid] = tanhf((z - m) * rsqrtf(var + 1e-5f) * se_lng[tid] + se_lnb[tid]);
    __syncthreads();
    if (tid < 128) {
        float s = se_b2[tid];
        for (int j = 0; j < 128; j++) s += se_w2[tid * 128 + j] * u[j];
        comb[tid] = s;
    }
    __syncthreads();
    // enc_time(t_start)
    float t0 = t_start[0];
    z = 0.f;
    if (tid < 128) z = te_b1[tid] + te_w1[tid] * t0;
    m = blocksum256(tid < 128 ? z : 0.f, red) * 0.0078125f;
    d = (tid < 128) ? z - m : 0.f;
    var = blocksum256(d * d, red) * 0.0078125f;
    if (tid < 128) u[tid] = tanhf((z - m) * rsqrtf(var + 1e-5f) * te_lng[tid] + te_lnb[tid]);
    __syncthreads();
    if (tid < 128) {
        float s = te_b2[tid];
        for (int j = 0; j < 128; j++) s += te_w2[tid * 128 + j] * u[j];
        comb[128 + tid] = s;
    }
    __syncthreads();
    {
        float s = hi_b[tid];
        for (int j = 0; j < 256; j++) s += hi_w[tid * 256 + j] * comb[j];
        g_h[tid] = s;
    }
}

// ---------------- per-step time-encoder tanh(LN(...)) vectors ----------------
__global__ void k_UT(const float* __restrict__ t_start, int steps,
                     const float* __restrict__ te_w1, const float* __restrict__ te_b1,
                     const float* __restrict__ te_lng, const float* __restrict__ te_lnb) {
    __shared__ float red[4];
    int tid = threadIdx.x;  // 128 threads
    float t0 = t_start[0];
    float fS = (float)steps;
    float w1 = te_w1[tid], b1 = te_b1[tid], gg = te_lng[tid], bb = te_lnb[tid];
    for (int i = blockIdx.x; i < steps; i += gridDim.x) {
        float t = t0 - (float)(i + 1) / fS;
        float z = b1 + w1 * t;
        float m = blocksum128(z, red) * 0.0078125f;
        float d = z - m;
        float var = blocksum128(d * d, red) * 0.0078125f;
        g_UT[i * 128 + tid] = tanhf(d * rsqrtf(var + 1e-5f) * gg + bb);
    }
}

// ---------------- T = UT @ M2^T + Kc  (small GEMM, parallel) ----------------
__global__ void k_TT(int steps) {
    __shared__ float UTs[16 * 128];
    int tid = threadIdx.x;
    int s0 = blockIdx.x * 16;
    int r = blockIdx.y * 256 + tid;
    for (int idx = tid; idx < 16 * 128; idx += 256) {
        int s = idx >> 7, j = idx & 127;
        UTs[idx] = (s0 + s < steps) ? g_UT[(s0 + s) * 128 + j] : 0.f;
    }
    __syncthreads();
    float acc[16];
#pragma unroll
    for (int s = 0; s < 16; s++) acc[s] = 0.f;
    for (int j = 0; j < 128; j++) {
        float mm = g_M2t[j * 1024 + r];
#pragma unroll
        for (int s = 0; s < 16; s++) acc[s] += mm * UTs[s * 128 + j];
    }
    float kc = g_Kc[r];
#pragma unroll
    for (int s = 0; s < 16; s++)
        if (s0 + s < steps) g_T[(s0 + s) * 1024 + r] = acc[s] + kc;
}

// ---------------- persistent sequential kernel ----------------
__global__ void __launch_bounds__(NT, 1) k_seq(
    const float* __restrict__ w_hh,
    const float* __restrict__ se_w1, const float* __restrict__ se_b1,
    const float* __restrict__ se_lng, const float* __restrict__ se_lnb,
    const float* __restrict__ sh_w1, const float* __restrict__ sh_b1,
    const float* __restrict__ sh_w2, const float* __restrict__ sh_b2,
    const float* __restrict__ sh_w3, const float* __restrict__ sh_b3,
    const float* __restrict__ dh_w1, const float* __restrict__ dh_b1,
    const float* __restrict__ dh_w2, const float* __restrict__ dh_b2,
    int steps, float* __restrict__ out) {
    extern __shared__ float sm[];
    float* Wg    = sm;            // [64][385]  gate rows (M1 | w_hh), padded
    float* Wh    = sm + 24640;    // [16][257]  head layer-1 rows, padded
    float* W2    = sm + 28752;    // [64][129]  sh_w2, padded
    float* w3s   = sm + 37008;    // [4][64]
    float* dw2s  = sm + 37264;    // [4][128]
    float* sew1  = sm + 37776;    // [128][4]
    float* seb1  = sm + 38288;    // [128]
    float* lng   = sm + 38416;    // [128]
    float* lnb   = sm + 38544;    // [128]
    float* xu    = sm + 38672;    // [384] = u(128) | h(256)
    float* vds   = sm + 39056;    // [256] = v1 | d1
    float* Ts    = sm + 39312;    // [64]
    float* gs    = sm + 39376;    // [64]
    float* gpart = sm + 39440;    // [8][64]
    float* hpart = sm + 39952;    // [16][16]
    float* vpart = sm + 40208;    // [4][64]
    float* v2s   = sm + 40464;    // [64]
    float* sb2   = sm + 40528;    // [64]
    float* hb    = sm + 40592;    // [16]
    float* cs    = sm + 40608;    // [16]  cell-state slice
    float* currs = sm + 40624;    // [4]
    float* shb3  = sm + 40628;    // [4]
    float* dhb2  = sm + 40632;    // [4]
    float* sd    = sm + 40636;    // [8] score(4) | denoise(4)
    float* red   = sm + 40644;    // [8]

    int tid = threadIdx.x, bid = blockIdx.x;

    // ---- prologue: stage weights into SMEM ----
    for (int idx = tid; idx < 64 * 384; idx += NT) {
        int r = idx / 384, j = idx - r * 384;
        int R = (r >> 4) * 256 + bid * 16 + (r & 15);
        float v = (j < 128) ? g_M1[R * 128 + j] : w_hh[R * 256 + (j - 128)];
        Wg[r * 385 + j] = v;
    }
    for (int idx = tid; idx < 16 * 256; idx += NT) {
        int l = idx >> 8, j = idx & 255;
        int RH = bid * 16 + l;
        Wh[l * 257 + j] = (RH < 128) ? sh_w1[RH * 256 + j] : dh_w1[(RH - 128) * 256 + j];
    }
    for (int idx = tid; idx < 64 * 128; idx += NT) {
        int rr = idx >> 7, j = idx & 127;
        W2[rr * 129 + j] = sh_w2[idx];
    }
    w3s[tid] = sh_w3[tid];
    for (int idx = tid; idx < 512; idx += NT) { dw2s[idx] = dh_w2[idx]; sew1[idx] = se_w1[idx]; }
    if (tid < 128) { seb1[tid] = se_b1[tid]; lng[tid] = se_lng[tid]; lnb[tid] = se_lnb[tid]; }
    if (tid < 64) sb2[tid] = sh_b2[tid];
    if (tid < 16) {
        int RH = bid * 16 + tid;
        hb[tid] = (RH < 128) ? sh_b1[RH] : dh_b1[RH - 128];
        cs[tid] = 0.f;
    }
    if (tid < 4) { currs[tid] = g_curr[tid]; shb3[tid] = sh_b3[tid]; dhb2[tid] = dh_b2[tid]; }
    xu[128 + tid] = g_h[tid];
    __syncthreads();

    float fS = (float)steps;
    for (int i = 0; i < steps; ++i) {
        // T-row prefetch (L2-resident)
        if (tid < 64) {
            int R = (tid >> 4) * 256 + bid * 16 + (tid & 15);
            Ts[tid] = g_T[i * 1024 + R];
        }
        // u = tanh(LN(se_w1 @ curr + se_b1))  — redundant per CTA
        float z = 0.f;
        if (tid < 128) {
            const float* w = sew1 + tid * 4;
            z = seb1[tid] + w[0] * currs[0] + w[1] * currs[1] + w[2] * currs[2] + w[3] * currs[3];
        }
        float m = blocksum256(tid < 128 ? z : 0.f, red) * 0.0078125f;
        float d = (tid < 128) ? z - m : 0.f;
        float var = blocksum256(d * d, red) * 0.0078125f;
        if (tid < 128) xu[tid] = tanhf((z - m) * rsqrtf(var + 1e-5f) * lng[tid] + lnb[tid]);
        __syncthreads();

        // gate GEMV: 64 rows x 384, 2 rows/thread, conflict-free
        {
            int part = tid >> 5, row2 = tid & 31;
            int j0 = part * 48;
            const float* wa = Wg + row2 * 385 + j0;
            const float* wb = Wg + (row2 + 32) * 385 + j0;
            const float* xp = xu + j0;
            float a0 = 0.f, a1 = 0.f;
#pragma unroll 8
            for (int k = 0; k < 48; k++) {
                float x = xp[k];
                a0 += wa[k] * x;
                a1 += wb[k] * x;
            }
            gpart[part * 64 + row2] = a0;
            gpart[part * 64 + row2 + 32] = a1;
        }
        __syncthreads();
        if (tid < 64) {
            float s = Ts[tid];
#pragma unroll
            for (int p = 0; p < 8; p++) s += gpart[p * 64 + tid];
            gs[tid] = s;
        }
        __syncthreads();

        // LSTM elementwise, publish h slice
        if (tid < 16) {
            float ig = gs[tid], fg = gs[16 + tid], ggt = gs[32 + tid], og = gs[48 + tid];
            float c = sigm(fg) * cs[tid] + sigm(ig) * tanhf(ggt);
            cs[tid] = c;
            float hn = sigm(og) * tanhf(c);
            __stcg(&g_h[bid * 16 + tid], hn);
            __threadfence();
        }
        gridbar(0, (unsigned)(i + 1));

        // gather full h_new
        xu[128 + tid] = __ldcg(&g_h[tid]);
        __syncthreads();

        // head layer-1: 16 rows x 256 per CTA
        {
            int p = tid >> 4, l = tid & 15;
            const float* w = Wh + l * 257 + p * 16;
            const float* x = xu + 128 + p * 16;
            float a = 0.f;
#pragma unroll
            for (int k = 0; k < 16; k++) a += w[k] * x[k];
            hpart[p * 16 + l] = a;
        }
        __syncthreads();
        if (tid < 16) {
            float s = hb[tid];
#pragma unroll
            for (int p = 0; p < 16; p++) s += hpart[p * 16 + tid];
            __stcg(&g_vd[bid * 16 + tid], tanhf(s));
            __threadfence();
        }
        gridbar(1, (unsigned)(i + 1));

        vds[tid] = __ldcg(&g_vd[tid]);
        __syncthreads();

        // v2 = tanh(sh_w2 @ v1 + sh_b2)  — redundant per CTA
        {
            int r = tid & 63, p = tid >> 6;
            const float* w = W2 + r * 129 + p * 32;
            const float* x = vds + p * 32;
            float a = 0.f;
#pragma unroll 8
            for (int k = 0; k < 32; k++) a += w[k] * x[k];
            vpart[p * 64 + r] = a;
        }
        __syncthreads();
        if (tid < 64) {
            float s = sb2[tid] + vpart[tid] + vpart[64 + tid] + vpart[128 + tid] + vpart[192 + tid];
            v2s[tid] = tanhf(s);
        }
        __syncthreads();

        // score = sh_w3 @ v2 + sh_b3 ; denoise = dh_w2 @ d1 + dh_b2
        {
            int w = tid >> 5, lane = tid & 31;
            float a;
            if (w < 4) {
                a = w3s[w * 64 + lane] * v2s[lane] + w3s[w * 64 + 32 + lane] * v2s[32 + lane];
            } else {
                int r = w - 4;
                const float* dw = dw2s + r * 128;
                const float* dx = vds + 128;
                a = dw[lane] * dx[lane] + dw[32 + lane] * dx[32 + lane]
                  + dw[64 + lane] * dx[64 + lane] + dw[96 + lane] * dx[96 + lane];
            }
#pragma unroll
            for (int o = 16; o > 0; o >>= 1) a += __shfl_down_sync(0xffffffffu, a, o);
            if (lane == 0) sd[w] = a + ((w < 4) ? shb3[w] : dhb2[w - 4]);
        }
        __syncthreads();

        // curr update + renorm (redundant, identical in all CTAs)
        if (tid == 0) {
            float ss = 0.02f * (1.0f - (float)i / fS);
            float nc[4], s2 = 0.f;
#pragma unroll
            for (int k = 0; k < 4; k++) { nc[k] = currs[k] + ss * (sd[4 + k] + 0.5f * sd[k]); s2 += nc[k] * nc[k]; }
            float inv = 1.0f / (sqrtf(s2) + 1e-8f);
#pragma unroll
            for (int k = 0; k < 4; k++) {
                float v = nc[k] * inv;
                currs[k] = v;
                if (bid == 0) out[(i + 1) * 4 + k] = v;
            }
        }
        __syncthreads();
    }
}

extern "C" void kernel_launch(void* const* d_in, const int* in_sizes, int n_in,
                              void* d_out, int out_size) {
    // input index map; "steps" (a scalar int) may or may not be materialized
    int off = (n_in >= 32) ? 4 : 3;
    const float* psi_re  = (const float*)d_in[0];
    const float* psi_im  = (const float*)d_in[1];
    const float* t_start = (const float*)d_in[2];
    const float* se_w1 = (const float*)d_in[off + 0];
    const float* se_b1 = (const float*)d_in[off + 1];
    const float* se_lng = (const float*)d_in[off + 2];
    const float* se_lnb = (const float*)d_in[off + 3];
    const float* se_w2 = (const float*)d_in[off + 4];
    const float* se_b2 = (const float*)d_in[off + 5];
    const float* te_w1 = (const float*)d_in[off + 6];
    const float* te_b1 = (const float*)d_in[off + 7];
    const float* te_lng = (const float*)d_in[off + 8];
    const float* te_lnb = (const float*)d_in[off + 9];
    const float* te_w2 = (const float*)d_in[off + 10];
    const float* te_b2 = (const float*)d_in[off + 11];
    const float* w_ih = (const float*)d_in[off + 12];
    const float* w_hh = (const float*)d_in[off + 13];
    const float* b_ih = (const float*)d_in[off + 14];
    const float* b_hh = (const float*)d_in[off + 15];
    const float* hi_w = (const float*)d_in[off + 16];
    const float* hi_b = (const float*)d_in[off + 17];
    const float* sh_w1 = (const float*)d_in[off + 18];
    const float* sh_b1 = (const float*)d_in[off + 19];
    const float* sh_w2 = (const float*)d_in[off + 20];
    const float* sh_b2 = (const float*)d_in[off + 21];
    const float* sh_w3 = (const float*)d_in[off + 22];
    const float* sh_b3 = (const float*)d_in[off + 23];
    const float* dh_w1 = (const float*)d_in[off + 24];
    const float* dh_b1 = (const float*)d_in[off + 25];
    const float* dh_w2 = (const float*)d_in[off + 26];
    const float* dh_b2 = (const float*)d_in[off + 27];
    float* out = (float*)d_out;

    int steps = out_size / 4 - 1;
    if (steps > MAXSTEPS) steps = MAXSTEPS;
    if (steps < 1) steps = 1;

    cudaFuncSetAttribute(k_seq, cudaFuncAttributeMaxDynamicSharedMemorySize, SMEM_BYTES);

    k_M<<<1024, 128>>>(w_ih, se_w2, te_w2, se_b2, te_b2, b_ih, b_hh);
    k_setup<<<1, 256>>>(psi_re, psi_im, t_start,
                        se_w1, se_b1, se_lng, se_lnb, se_w2, se_b2,
                        te_w1, te_b1, te_lng, te_lnb, te_w2, te_b2,
                        hi_w, hi_b, out);
    k_UT<<<256, 128>>>(t_start, steps, te_w1, te_b1, te_lng, te_lnb);
    k_TT<<<dim3((steps + 15) / 16, 4), 256>>>(steps);
    k_seq<<<G, NT, SMEM_BYTES>>>(w_hh,
                                 se_w1, se_b1, se_lng, se_lnb,
                                 sh_w1, sh_b1, sh_w2, sh_b2, sh_w3, sh_b3,
                                 dh_w1, dh_b1, dh_w2, dh_b2,
                                 steps, out);
}

// round 6
// speedup vs baseline: 1.3617x; 1.3617x over previous
#include <cuda_runtime.h>
#include <math.h>

#define NT 256
#define G 16
#define MAXSTEPS 4096
#define SMEM_FLOATS 41212
#define SMEM_BYTES (SMEM_FLOATS * 4)

// ---------------- persistent device state ----------------
__device__ float g_T[MAXSTEPS * 1024];   // per-step time-side gate contribution + folded biases
__device__ float g_UT[MAXSTEPS * 128];   // per-step tanh(LN(time enc layer1))
__device__ float g_M1[1024 * 128];       // w_ih[:, :128] @ se_w2
__device__ float g_M2t[128 * 1024];      // transpose of w_ih[:, 128:] @ te_w2
__device__ float g_Kc[1024];             // folded constant bias
__device__ float g_h0[256];              // initial hidden state (setup -> seq)
__device__ float g_curr[4];
__device__ float g_h2[2][256];           // parity-buffered h broadcast
__device__ float g_P[2][G * 256];        // parity-buffered head-1 partials
__device__ unsigned g_flag[G];           // per-CTA publish flags (monotonic per launch)

__device__ __forceinline__ float sigm(float x) { return 1.0f / (1.0f + expf(-x)); }

__device__ __forceinline__ void st_release(unsigned* p, unsigned v) {
    asm volatile("st.release.gpu.global.u32 [%0], %1;" :: "l"(p), "r"(v) : "memory");
}

__device__ __forceinline__ unsigned ld_acquire(const unsigned* p) {
    unsigned v;
    asm volatile("ld.acquire.gpu.global.u32 %0, [%1];" : "=r"(v) : "l"(p) : "memory");
    return v;
}

// sum over 128 active threads (tid<128 pass value, others 0); all 256 call.
__device__ __forceinline__ float blocksum128(float v, float* red) {
    int lane = threadIdx.x & 31, w = threadIdx.x >> 5;
#pragma unroll
    for (int o = 16; o > 0; o >>= 1) v += __shfl_down_sync(0xffffffffu, v, o);
    if (lane == 0) red[w] = v;
    __syncthreads();
    float s = red[0] + red[1] + red[2] + red[3];
    __syncthreads();
    return s;
}

// ---------------- precompute M1, M2t, Kc ----------------
__global__ void k_M(const float* __restrict__ w_ih, const float* __restrict__ se_w2,
                    const float* __restrict__ te_w2, const float* __restrict__ se_b2,
                    const float* __restrict__ te_b2, const float* __restrict__ b_ih,
                    const float* __restrict__ b_hh) {
    int r = blockIdx.x, j = threadIdx.x;  // 1024 x 128
    const float* wr = w_ih + r * 256;
    float s1 = 0.f, s2 = 0.f;
    for (int i = 0; i < 128; i++) s1 += wr[i] * se_w2[i * 128 + j];
    for (int i = 0; i < 128; i++) s2 += wr[128 + i] * te_w2[i * 128 + j];
    g_M1[r * 128 + j] = s1;
    g_M2t[j * 1024 + r] = s2;
    if (j == 0) {
        float kc = b_ih[r] + b_hh[r];
        for (int i = 0; i < 128; i++) kc += wr[i] * se_b2[i] + wr[128 + i] * te_b2[i];
        g_Kc[r] = kc;
    }
}

// ---------------- setup: flags, curr0, out row0, h0 ----------------
__global__ void k_setup(const float* __restrict__ psi_re, const float* __restrict__ psi_im,
                        const float* __restrict__ t_start,
                        const float* __restrict__ se_w1, const float* __restrict__ se_b1,
                        const float* __restrict__ se_lng, const float* __restrict__ se_lnb,
                        const float* __restrict__ se_w2, const float* __restrict__ se_b2,
                        const float* __restrict__ te_w1, const float* __restrict__ te_b1,
                        const float* __restrict__ te_lng, const float* __restrict__ te_lnb,
                        const float* __restrict__ te_w2, const float* __restrict__ te_b2,
                        const float* __restrict__ hi_w, const float* __restrict__ hi_b,
                        float* __restrict__ out) {
    __shared__ float curr[4], u[128], comb[256], red[8];
    int tid = threadIdx.x;
    if (tid < G) g_flag[tid] = 0u;
    if (tid < 4) {
        float v = (tid < 2) ? psi_re[tid] : psi_im[tid - 2];
        curr[tid] = v; g_curr[tid] = v; out[tid] = v;
    }
    __syncthreads();
    float z = 0.f;
    if (tid < 128) {
        const float* w = se_w1 + tid * 4;
        z = se_b1[tid] + w[0] * curr[0] + w[1] * curr[1] + w[2] * curr[2] + w[3] * curr[3];
    }
    float m = blocksum128(tid < 128 ? z : 0.f, red) * 0.0078125f;
    float d = (tid < 128) ? z - m : 0.f;
    float var = blocksum128(d * d, red) * 0.0078125f;
    if (tid < 128) u[tid] = tanhf((z - m) * rsqrtf(var + 1e-5f) * se_lng[tid] + se_lnb[tid]);
    __syncthreads();
    if (tid < 128) {
        float s = se_b2[tid];
        for (int j = 0; j < 128; j++) s += se_w2[tid * 128 + j] * u[j];
        comb[tid] = s;
    }
    __syncthreads();
    float t0 = t_start[0];
    z = 0.f;
    if (tid < 128) z = te_b1[tid] + te_w1[tid] * t0;
    m = blocksum128(tid < 128 ? z : 0.f, red) * 0.0078125f;
    d = (tid < 128) ? z - m : 0.f;
    var = blocksum128(d * d, red) * 0.0078125f;
    if (tid < 128) u[tid] = tanhf((z - m) * rsqrtf(var + 1e-5f) * te_lng[tid] + te_lnb[tid]);
    __syncthreads();
    if (tid < 128) {
        float s = te_b2[tid];
        for (int j = 0; j < 128; j++) s += te_w2[tid * 128 + j] * u[j];
        comb[128 + tid] = s;
    }
    __syncthreads();
    {
        float s = hi_b[tid];
        for (int j = 0; j < 256; j++) s += hi_w[tid * 256 + j] * comb[j];
        g_h0[tid] = s;
    }
}

// ---------------- per-step time-encoder tanh(LN(.)) — exact two-pass ----------
__global__ void k_UT(const float* __restrict__ t_start, int steps,
                     const float* __restrict__ te_w1, const float* __restrict__ te_b1,
                     const float* __restrict__ te_lng, const float* __restrict__ te_lnb) {
    __shared__ float red[4];
    int tid = threadIdx.x;  // 128
    float t0 = t_start[0];
    float fS = (float)steps;
    float w1 = te_w1[tid], b1 = te_b1[tid], gg = te_lng[tid], bb = te_lnb[tid];
    for (int i = blockIdx.x; i < steps; i += gridDim.x) {
        float t = t0 - (float)(i + 1) / fS;
        float z = b1 + w1 * t;
        float m = blocksum128(z, red) * 0.0078125f;
        float d = z - m;
        float var = blocksum128(d * d, red) * 0.0078125f;
        g_UT[i * 128 + tid] = tanhf(d * rsqrtf(var + 1e-5f) * gg + bb);
        __syncthreads();
    }
}

// ---------------- T = UT @ M2^T + Kc ----------------
__global__ void k_TT(int steps) {
    __shared__ float UTs[16 * 128];
    int tid = threadIdx.x;
    int s0 = blockIdx.x * 16;
    int r = blockIdx.y * 256 + tid;
    for (int idx = tid; idx < 16 * 128; idx += 256) {
        int s = idx >> 7, j = idx & 127;
        UTs[idx] = (s0 + s < steps) ? g_UT[(s0 + s) * 128 + j] : 0.f;
    }
    __syncthreads();
    float acc[16];
#pragma unroll
    for (int s = 0; s < 16; s++) acc[s] = 0.f;
    for (int j = 0; j < 128; j++) {
        float mm = g_M2t[j * 1024 + r];
#pragma unroll
        for (int s = 0; s < 16; s++) acc[s] += mm * UTs[s * 128 + j];
    }
    float kc = g_Kc[r];
#pragma unroll
    for (int s = 0; s < 16; s++)
        if (s0 + s < steps) g_T[(s0 + s) * 1024 + r] = acc[s] + kc;
}

// ---------------- persistent sequential kernel: ONE barrier per step ----------
__global__ void __launch_bounds__(NT, 1) k_seq(
    const float* __restrict__ w_hh,
    const float* __restrict__ se_w1, const float* __restrict__ se_b1,
    const float* __restrict__ se_lng, const float* __restrict__ se_lnb,
    const float* __restrict__ sh_w1, const float* __restrict__ sh_b1,
    const float* __restrict__ sh_w2, const float* __restrict__ sh_b2,
    const float* __restrict__ sh_w3, const float* __restrict__ sh_b3,
    const float* __restrict__ dh_w1, const float* __restrict__ dh_b1,
    const float* __restrict__ dh_w2, const float* __restrict__ dh_b2,
    int steps, float* __restrict__ out) {
    extern __shared__ float sm[];
    float* Wg    = sm;            // [64][388]  gate rows (M1 | w_hh), f4-padded
    float* WhC   = sm + 24832;    // [256][17]  head-1 column slice (this CTA's 16 h-cols)
    float* W2    = sm + 29184;    // [64][132]  sh_w2, f4-padded
    float* w3s   = sm + 37632;    // [4][64]
    float* dw2s  = sm + 37888;    // [4][128]
    float* sew1  = sm + 38400;    // [128][4]
    float* seb1  = sm + 38912;    // [128]
    float* lng   = sm + 39040;    // [128]
    float* lnb   = sm + 39168;    // [128]
    float* hbias = sm + 39296;    // [256]  sh_b1 | dh_b1
    float* x     = sm + 39552;    // [384]  u(128) | h(256)
    float* vd    = sm + 39936;    // [256]  v1 | d1 (post-tanh, after partial sum)
    float* gpart = sm + 40192;    // [8][64]
    float* vpart = sm + 40704;    // [4][64]
    float* v2s   = sm + 40960;    // [64]
    float* sb2   = sm + 41024;    // [64]
    float* hs    = sm + 41088;    // [16]  new h slice
    float* cs    = sm + 41104;    // [16]  cell state slice
    float* currs = sm + 41120;    // [4]
    float* shb3  = sm + 41124;    // [4]
    float* dhb2  = sm + 41128;    // [4]
    float* sd    = sm + 41132;    // [8]
    float* red   = sm + 41140;    // [8]
    float* gs    = sm + 41148;    // [64]

    int tid = threadIdx.x, bid = blockIdx.x;

    // ---- prologue: stage weights ----
    for (int idx = tid; idx < 64 * 384; idx += NT) {
        int r = idx / 384, j = idx - r * 384;
        int R = (r >> 4) * 256 + bid * 16 + (r & 15);
        float v = (j < 128) ? g_M1[R * 128 + j] : w_hh[R * 256 + (j - 128)];
        Wg[r * 388 + j] = v;
    }
    for (int idx = tid; idx < 256 * 16; idx += NT) {
        int r = idx >> 4, l = idx & 15;
        int col = bid * 16 + l;
        WhC[r * 17 + l] = (r < 128) ? sh_w1[r * 256 + col] : dh_w1[(r - 128) * 256 + col];
    }
    for (int idx = tid; idx < 64 * 128; idx += NT) {
        int rr = idx >> 7, j = idx & 127;
        W2[rr * 132 + j] = sh_w2[idx];
    }
    w3s[tid] = sh_w3[tid];
    for (int idx = tid; idx < 512; idx += NT) { dw2s[idx] = dh_w2[idx]; sew1[idx] = se_w1[idx]; }
    if (tid < 128) { seb1[tid] = se_b1[tid]; lng[tid] = se_lng[tid]; lnb[tid] = se_lnb[tid]; }
    hbias[tid] = (tid < 128) ? sh_b1[tid] : dh_b1[tid - 128];
    if (tid < 64) sb2[tid] = sh_b2[tid];
    if (tid < 16) cs[tid] = 0.f;
    if (tid < 4) { currs[tid] = g_curr[tid]; shb3[tid] = sh_b3[tid]; dhb2[tid] = dh_b2[tid]; }
    x[128 + tid] = g_h0[tid];
    __syncthreads();

    const float* Trow = g_T + (tid >> 4) * 256 + bid * 16 + (tid & 15);
    float fS = (float)steps;

    for (int i = 0; i < steps; ++i) {
        int p = i & 1;
        // T-row into register (L2-resident; latency hidden under u + gate)
        float tval = 0.f;
        if (tid < 64) tval = Trow[i * 1024];

        // u = tanh(LN(se_w1 @ curr + se_b1)); fused mean/var (round-2 proven)
        float z = 0.f;
        if (tid < 128) {
            const float* w = sew1 + tid * 4;
            z = seb1[tid] + w[0] * currs[0] + w[1] * currs[1] + w[2] * currs[2] + w[3] * currs[3];
        }
        {
            int lane = tid & 31, w = tid >> 5;
            float s1 = z, s2 = z * z;
#pragma unroll
            for (int o = 16; o > 0; o >>= 1) {
                s1 += __shfl_down_sync(0xffffffffu, s1, o);
                s2 += __shfl_down_sync(0xffffffffu, s2, o);
            }
            if (lane == 0 && w < 4) { red[w * 2] = s1; red[w * 2 + 1] = s2; }
        }
        __syncthreads();
        if (tid < 128) {
            float m = (red[0] + red[2] + red[4] + red[6]) * 0.0078125f;
            float q = (red[1] + red[3] + red[5] + red[7]) * 0.0078125f;
            float var = q - m * m;
            x[tid] = tanhf((z - m) * rsqrtf(var + 1e-5f) * lng[tid] + lnb[tid]);
        }
        __syncthreads();

        // gate GEMV: 64 rows x 384 (x = u | h_prev), vectorized, conflict-free
        {
            int part = tid >> 5, row2 = tid & 31;
            int j0 = part * 48;
            const float4* wa = (const float4*)(Wg + row2 * 388 + j0);
            const float4* wb = (const float4*)(Wg + (row2 + 32) * 388 + j0);
            const float4* xp = (const float4*)(x + j0);
            float a0 = 0.f, a1 = 0.f;
#pragma unroll
            for (int k = 0; k < 12; k++) {
                float4 x4 = xp[k];
                float4 w4 = wa[k];
                a0 += w4.x * x4.x + w4.y * x4.y + w4.z * x4.z + w4.w * x4.w;
                float4 v4 = wb[k];
                a1 += v4.x * x4.x + v4.y * x4.y + v4.z * x4.z + v4.w * x4.w;
            }
            gpart[part * 64 + row2] = a0;
            gpart[part * 64 + row2 + 32] = a1;
        }
        __syncthreads();
        if (tid < 64) {
            float s = tval;
#pragma unroll
            for (int q = 0; q < 8; q++) s += gpart[q * 64 + tid];
            gs[tid] = s;
        }
        __syncthreads();

        // LSTM elementwise -> h slice (16 values)
        if (tid < 16) {
            float ig = gs[tid], fg = gs[16 + tid], ggt = gs[32 + tid], og = gs[48 + tid];
            float c = sigm(fg) * cs[tid] + sigm(ig) * tanhf(ggt);
            cs[tid] = c;
            float hn = sigm(og) * tanhf(c);
            hs[tid] = hn;
            __stcg(&g_h2[p][bid * 16 + tid], hn);  // publish h slice early
        }
        __syncthreads();

        // head-1 partial from OWN h slice: P[tid] = sum_l WhC[tid][l] * hs[l]
        {
            const float* w = WhC + tid * 17;
            float a = 0.f;
#pragma unroll
            for (int l = 0; l < 16; l++) a += w[l] * hs[l];
            __stcg(&g_P[p][bid * 256 + tid], a);  // publish partial
        }
        // RELEASE: all writers fence, CTA-sync, then tid0 raises flag with release.
        __threadfence();
        __syncthreads();
        if (tid == 0) st_release(&g_flag[bid], (unsigned)(i + 1));

        // ---- single grid barrier: acquire-spin on all 16 flags ----
        if (tid < G) {
            unsigned tgt = (unsigned)(i + 1);
            while (ld_acquire(&g_flag[tid]) < tgt) { }
        }
        __syncthreads();

        // gather full h (for next step's gate) and reduce head-1 partials
        x[128 + tid] = __ldcg(&g_h2[p][tid]);
        {
            float s = hbias[tid];
            const float* pp = &g_P[p][tid];
#pragma unroll
            for (int b = 0; b < G; b++) s += __ldcg(pp + b * 256);
            vd[tid] = tanhf(s);
        }
        __syncthreads();

        // v2 = tanh(sh_w2 @ v1 + sh_b2) — redundant per CTA, vectorized
        {
            int r = tid & 63, q = tid >> 6;
            const float4* w = (const float4*)(W2 + r * 132 + q * 32);
            const float4* xx = (const float4*)(vd + q * 32);
            float a = 0.f;
#pragma unroll
            for (int k = 0; k < 8; k++) {
                float4 w4 = w[k], x4 = xx[k];
                a += w4.x * x4.x + w4.y * x4.y + w4.z * x4.z + w4.w * x4.w;
            }
            vpart[q * 64 + r] = a;
        }
        __syncthreads();
        if (tid < 64) {
            float s = sb2[tid] + vpart[tid] + vpart[64 + tid] + vpart[128 + tid] + vpart[192 + tid];
            v2s[tid] = tanhf(s);
        }
        __syncthreads();

        // score = sh_w3 @ v2 + b ; denoise = dh_w2 @ d1 + b
        {
            int w = tid >> 5, lane = tid & 31;
            float a;
            if (w < 4) {
                a = w3s[w * 64 + lane] * v2s[lane] + w3s[w * 64 + 32 + lane] * v2s[32 + lane];
            } else {
                int r = w - 4;
                const float* dw = dw2s + r * 128;
                const float* dx = vd + 128;
                a = dw[lane] * dx[lane] + dw[32 + lane] * dx[32 + lane]
                  + dw[64 + lane] * dx[64 + lane] + dw[96 + lane] * dx[96 + lane];
            }
#pragma unroll
            for (int o = 16; o > 0; o >>= 1) a += __shfl_down_sync(0xffffffffu, a, o);
            if (lane == 0) sd[w] = a + ((w < 4) ? shb3[w] : dhb2[w - 4]);
        }
        __syncthreads();

        // curr update + renorm (identical in all CTAs)
        if (tid == 0) {
            float ss = 0.02f * (1.0f - (float)i / fS);
            float nc[4], s2 = 0.f;
#pragma unroll
            for (int k = 0; k < 4; k++) {
                nc[k] = currs[k] + ss * (sd[4 + k] + 0.5f * sd[k]);
                s2 += nc[k] * nc[k];
            }
            float inv = 1.0f / (sqrtf(s2) + 1e-8f);
#pragma unroll
            for (int k = 0; k < 4; k++) {
                float v = nc[k] * inv;
                currs[k] = v;
                if (bid == 0) out[(i + 1) * 4 + k] = v;
            }
        }
        __syncthreads();
    }
}

extern "C" void kernel_launch(void* const* d_in, const int* in_sizes, int n_in,
                              void* d_out, int out_size) {
    int off = (n_in >= 32) ? 4 : 3;
    const float* psi_re  = (const float*)d_in[0];
    const float* psi_im  = (const float*)d_in[1];
    const float* t_start = (const float*)d_in[2];
    const float* se_w1 = (const float*)d_in[off + 0];
    const float* se_b1 = (const float*)d_in[off + 1];
    const float* se_lng = (const float*)d_in[off + 2];
    const float* se_lnb = (const float*)d_in[off + 3];
    const float* se_w2 = (const float*)d_in[off + 4];
    const float* se_b2 = (const float*)d_in[off + 5];
    const float* te_w1 = (const float*)d_in[off + 6];
    const float* te_b1 = (const float*)d_in[off + 7];
    const float* te_lng = (const float*)d_in[off + 8];
    const float* te_lnb = (const float*)d_in[off + 9];
    const float* te_w2 = (const float*)d_in[off + 10];
    const float* te_b2 = (const float*)d_in[off + 11];
    const float* w_ih = (const float*)d_in[off + 12];
    const float* w_hh = (const float*)d_in[off + 13];
    const float* b_ih = (const float*)d_in[off + 14];
    const float* b_hh = (const float*)d_in[off + 15];
    const float* hi_w = (const float*)d_in[off + 16];
    const float* hi_b = (const float*)d_in[off + 17];
    const float* sh_w1 = (const float*)d_in[off + 18];
    const float* sh_b1 = (const float*)d_in[off + 19];
    const float* sh_w2 = (const float*)d_in[off + 20];
    const float* sh_b2 = (const float*)d_in[off + 21];
    const float* sh_w3 = (const float*)d_in[off + 22];
    const float* sh_b3 = (const float*)d_in[off + 23];
    const float* dh_w1 = (const float*)d_in[off + 24];
    const float* dh_b1 = (const float*)d_in[off + 25];
    const float* dh_w2 = (const float*)d_in[off + 26];
    const float* dh_b2 = (const float*)d_in[off + 27];
    float* out = (float*)d_out;

    int steps = out_size / 4 - 1;
    if (steps > MAXSTEPS) steps = MAXSTEPS;
    if (steps < 1) steps = 1;

    cudaFuncSetAttribute(k_seq, cudaFuncAttributeMaxDynamicSharedMemorySize, SMEM_BYTES);

    k_M<<<1024, 128>>>(w_ih, se_w2, te_w2, se_b2, te_b2, b_ih, b_hh);
    k_setup<<<1, 256>>>(psi_re, psi_im, t_start,
                        se_w1, se_b1, se_lng, se_lnb, se_w2, se_b2,
                        te_w1, te_b1, te_lng, te_lnb, te_w2, te_b2,
                        hi_w, hi_b, out);
    k_UT<<<256, 128>>>(t_start, steps, te_w1, te_b1, te_lng, te_lnb);
    k_TT<<<dim3((steps + 15) / 16, 4), 256>>>(steps);
    k_seq<<<G, NT, SMEM_BYTES>>>(w_hh,
                                 se_w1, se_b1, se_lng, se_lnb,
                                 sh_w1, sh_b1, sh_w2, sh_b2, sh_w3, sh_b3,
                                 dh_w1, dh_b1, dh_w2, dh_b2,
                                 steps, out);
}